// round 8
// baseline (speedup 1.0000x reference)
#include <cuda_runtime.h>
#include <cuda_fp16.h>
#include <math.h>

#define N_NODES 100000
#define N_EDGES 1600000
#define H 64
#define MB 128           // mega-kernel blocks (<=148 SMs, all resident)
#define MT 1024          // mega-kernel threads/block
#define EPT 13           // ceil(N_EDGES / (MB*MT)) = ceil(1.6M/131072)
#define SCAN_B 98        // ceil(N_NODES / 1024)

// Scratch (device globals — no allocation allowed)
__device__ int    g_degi[N_NODES];
__device__ float  g_dinv[N_NODES];
__device__ int    g_rowptr[N_NODES];       // partial (exclusive within chunk)
__device__ int    g_rowabs[N_NODES + 1];   // absolute CSR rowptr (for pull)
__device__ int    g_bsum[MB];
__device__ int2   g_edge[N_EDGES];         // {src, norm-as-bits}
__device__ __half g_yh[(size_t)N_NODES * H];   // y = xW (fp16, gather target)
__device__ __half g_xh[(size_t)N_NODES * H];   // intermediate layer output (fp16)

__device__ volatile int g_barc;   // zero-init; returns to 0 after each barrier
__device__ volatile int g_barg;   // generation counter (monotonic across calls)

#define FMA2(acc, a, b) \
    asm("fma.rn.f32x2 %0, %1, %2, %0;" : "+l"(acc) : "l"(a), "l"(b))

__device__ __forceinline__ void grid_barrier() {
    __syncthreads();
    if (threadIdx.x == 0) {
        int gen = g_barg;
        __threadfence();
        if (atomicAdd((int*)&g_barc, 1) == MB - 1) {
            g_barc = 0;
            __threadfence();
            g_barg = gen + 1;   // release
        } else {
            while (g_barg == gen) { }
            __threadfence();    // acquire
        }
    }
    __syncthreads();
}

// One kernel: zero -> hist(ranks in regs) -> scan(+dinv) -> top-scan -> fill.
__global__ void __launch_bounds__(MT, 1) csr_kernel(const int* __restrict__ ei)
{
    __shared__ int s[MT];
    __shared__ int s2[128];
    __shared__ int s_boff[128];

    const int t = threadIdx.x;
    const int b = blockIdx.x;
    const int gtid = b * MT + t;

    // ---- Phase 1: zero degrees ----
    if (gtid < N_NODES) g_degi[gtid] = 0;
    grid_barrier();

    // ---- Phase 2: histogram; keep each edge's rank in registers ----
    int rank[EPT];
#pragma unroll
    for (int k = 0; k < EPT; k++) {
        int e = gtid + k * (MB * MT);
        rank[k] = 0;
        if (e < N_EDGES) {
            int d = ei[N_EDGES + e];
            rank[k] = atomicAdd(&g_degi[d], 1);
        }
    }
    grid_barrier();

    // ---- Phase 3: per-chunk scan of degrees + dinv (blocks 0..97) ----
    if (b < SCAN_B) {
        int i = b * MT + t;
        int v = (i < N_NODES) ? g_degi[i] : 0;
        if (i < N_NODES) g_dinv[i] = rsqrtf((float)(v + 1));
        s[t] = v;
        __syncthreads();
        for (int off = 1; off < MT; off <<= 1) {
            int tmp = 0;
            if (t >= off) tmp = s[t - off];
            __syncthreads();
            if (t >= off) s[t] += tmp;
            __syncthreads();
        }
        if (i < N_NODES) g_rowptr[i] = s[t] - v;  // exclusive within chunk
        if (t == MT - 1) g_bsum[b] = s[t];
    }
    grid_barrier();

    // ---- Phase 4: every block redundantly top-scans the 98 chunk sums ----
    if (t < 128) s2[t] = (t < SCAN_B) ? g_bsum[t] : 0;
    __syncthreads();
    {
        int v2 = (t < 128) ? s2[t] : 0;
        for (int off = 1; off < 128; off <<= 1) {
            int tmp = 0;
            if (t >= off && t < 128) tmp = s2[t - off];
            __syncthreads();
            if (t >= off && t < 128) s2[t] += tmp;
            __syncthreads();
        }
        if (t < 128) s_boff[t] = s2[t] - v2;  // exclusive block offsets
    }
    __syncthreads();

    // blocks 0..97 emit absolute rowptr for the pull kernels
    if (b < SCAN_B) {
        int i = b * MT + t;
        if (i < N_NODES) g_rowabs[i] = g_rowptr[i] + s_boff[b];
    }
    if (b == 0 && t == 0) g_rowabs[N_NODES] = N_EDGES;

    // ---- Phase 5: fill CSR from register ranks (reads partial rowptr + smem boff,
    //      never the in-flight rowabs) ----
#pragma unroll
    for (int k = 0; k < EPT; k++) {
        int e = gtid + k * (MB * MT);
        if (e < N_EDGES) {
            int sr = ei[e];
            int d  = ei[N_EDGES + e];
            int p = g_rowptr[d] + s_boff[d >> 10] + rank[k];
            int2 m;
            m.x = sr;
            m.y = __float_as_int(g_dinv[sr] * g_dinv[d]);
            g_edge[p] = m;
        }
    }
}

// y = x @ W (fp16 out). xsel: 0 = fp32 embeddings, 1 = fp16 g_xh.
__global__ void __launch_bounds__(128, 4) gemm_kernel(
    const float* __restrict__ x_ext, const float* __restrict__ W, int xsel)
{
    __shared__ float4 Ws[64][16];  // W row-major [k][c4]

    int tid = threadIdx.x;
    for (int i = tid; i < 64 * 16; i += 128)
        ((float4*)Ws)[i] = ((const float4*)W)[i];
    __syncthreads();

    int row = blockIdx.x * 128 + tid;
    if (row >= N_NODES) return;

    unsigned long long acc[32];
#pragma unroll
    for (int c = 0; c < 32; c++) acc[c] = 0ull;

    if (xsel == 0) {
        const float4* x4 = (const float4*)x_ext + (size_t)row * 16;
#pragma unroll 4
        for (int k4 = 0; k4 < 16; k4++) {
            float4 xv = x4[k4];
            float xsv[4];
            xsv[0] = xv.x; xsv[1] = xv.y; xsv[2] = xv.z; xsv[3] = xv.w;
#pragma unroll
            for (int j = 0; j < 4; j++) {
                unsigned long long xk2;
                asm("mov.b64 %0, {%1, %1};" : "=l"(xk2) : "f"(xsv[j]));
                int k = k4 * 4 + j;
                const ulonglong2* wrow = (const ulonglong2*)&Ws[k][0];
#pragma unroll
                for (int c = 0; c < 16; c++) {
                    ulonglong2 w = wrow[c];
                    FMA2(acc[2 * c],     xk2, w.x);
                    FMA2(acc[2 * c + 1], xk2, w.y);
                }
            }
        }
    } else {
        const uint4* xr = (const uint4*)(g_xh + (size_t)row * H);  // 8 uint4
#pragma unroll 2
        for (int u = 0; u < 8; u++) {
            uint4 v = xr[u];
            const __half2* hp = (const __half2*)&v;
            float xsv[8];
#pragma unroll
            for (int p = 0; p < 4; p++) {
                float2 f = __half22float2(hp[p]);
                xsv[2 * p] = f.x; xsv[2 * p + 1] = f.y;
            }
#pragma unroll
            for (int j = 0; j < 8; j++) {
                unsigned long long xk2;
                asm("mov.b64 %0, {%1, %1};" : "=l"(xk2) : "f"(xsv[j]));
                int k = u * 8 + j;
                const ulonglong2* wrow = (const ulonglong2*)&Ws[k][0];
#pragma unroll
                for (int c = 0; c < 16; c++) {
                    ulonglong2 w = wrow[c];
                    FMA2(acc[2 * c],     xk2, w.x);
                    FMA2(acc[2 * c + 1], xk2, w.y);
                }
            }
        }
    }

    uint4* yrow = (uint4*)(g_yh + (size_t)row * H);
#pragma unroll
    for (int u = 0; u < 8; u++) {
        uint4 o;
        unsigned r[4];
#pragma unroll
        for (int j = 0; j < 4; j++) {
            float lo, hi;
            asm("mov.b64 {%0, %1}, %2;" : "=f"(lo), "=f"(hi) : "l"(acc[u * 4 + j]));
            __half2 hv = __floats2half2_rn(lo, hi);
            r[j] = *(unsigned*)&hv;
        }
        o.x = r[0]; o.y = r[1]; o.z = r[2]; o.w = r[3];
        yrow[u] = o;
    }
}

// Pull: one warp per dst. q = lane&7 (16B = 8 fp16 cols), h = lane>>3 (4 edge slots).
// t = sum_e y[src_e]*norm_e + y[dst]*dinv^2 + b   (fp32 accumulate)
// mode==1: g_xh[dst] = t (fp16) ; mode==0: out[dst] = t (fp32, final)
__global__ void __launch_bounds__(256) pull_kernel(
    const float* __restrict__ bias, float* __restrict__ out_ext, int mode)
{
    int warp = (blockIdx.x * 256 + threadIdx.x) >> 5;   // grid exact: N_NODES warps
    int dst = warp;
    int lane = threadIdx.x & 31;
    int q = lane & 7;
    int h = lane >> 3;

    int beg = g_rowabs[dst];
    int end = g_rowabs[dst + 1];

    const uint4* y16 = (const uint4*)g_yh;  // 8 uint4 per row

    float4 a0 = make_float4(0.f, 0.f, 0.f, 0.f);
    float4 a1 = make_float4(0.f, 0.f, 0.f, 0.f);

    for (int j = beg + h; j < end; j += 4) {
        int2 m = g_edge[j];
        float nm = __int_as_float(m.y);
        uint4 v = y16[(size_t)m.x * 8 + q];
        const __half2* hp = (const __half2*)&v;
        float2 f0 = __half22float2(hp[0]);
        float2 f1 = __half22float2(hp[1]);
        float2 f2 = __half22float2(hp[2]);
        float2 f3 = __half22float2(hp[3]);
        a0.x = fmaf(f0.x, nm, a0.x); a0.y = fmaf(f0.y, nm, a0.y);
        a0.z = fmaf(f1.x, nm, a0.z); a0.w = fmaf(f1.y, nm, a0.w);
        a1.x = fmaf(f2.x, nm, a1.x); a1.y = fmaf(f2.y, nm, a1.y);
        a1.z = fmaf(f3.x, nm, a1.z); a1.w = fmaf(f3.y, nm, a1.w);
    }

#pragma unroll
    for (int off = 8; off < 32; off <<= 1) {
        a0.x += __shfl_xor_sync(0xFFFFFFFFu, a0.x, off);
        a0.y += __shfl_xor_sync(0xFFFFFFFFu, a0.y, off);
        a0.z += __shfl_xor_sync(0xFFFFFFFFu, a0.z, off);
        a0.w += __shfl_xor_sync(0xFFFFFFFFu, a0.w, off);
        a1.x += __shfl_xor_sync(0xFFFFFFFFu, a1.x, off);
        a1.y += __shfl_xor_sync(0xFFFFFFFFu, a1.y, off);
        a1.z += __shfl_xor_sync(0xFFFFFFFFu, a1.z, off);
        a1.w += __shfl_xor_sync(0xFFFFFFFFu, a1.w, off);
    }

    if (h == 0) {
        float di = g_dinv[dst];
        float s2 = di * di;
        uint4 v = y16[(size_t)dst * 8 + q];
        const __half2* hp = (const __half2*)&v;
        float2 f0 = __half22float2(hp[0]);
        float2 f1 = __half22float2(hp[1]);
        float2 f2 = __half22float2(hp[2]);
        float2 f3 = __half22float2(hp[3]);
        float4 bv0 = ((const float4*)bias)[q * 2];
        float4 bv1 = ((const float4*)bias)[q * 2 + 1];
        float4 t0, t1;
        t0.x = fmaf(f0.x, s2, a0.x) + bv0.x;
        t0.y = fmaf(f0.y, s2, a0.y) + bv0.y;
        t0.z = fmaf(f1.x, s2, a0.z) + bv0.z;
        t0.w = fmaf(f1.y, s2, a0.w) + bv0.w;
        t1.x = fmaf(f2.x, s2, a1.x) + bv1.x;
        t1.y = fmaf(f2.y, s2, a1.y) + bv1.y;
        t1.z = fmaf(f3.x, s2, a1.z) + bv1.z;
        t1.w = fmaf(f3.y, s2, a1.w) + bv1.w;
        if (mode) {
            uint4 o;
            __half2 h0 = __floats2half2_rn(t0.x, t0.y);
            __half2 h1 = __floats2half2_rn(t0.z, t0.w);
            __half2 h2 = __floats2half2_rn(t1.x, t1.y);
            __half2 h3 = __floats2half2_rn(t1.z, t1.w);
            o.x = *(unsigned*)&h0; o.y = *(unsigned*)&h1;
            o.z = *(unsigned*)&h2; o.w = *(unsigned*)&h3;
            ((uint4*)g_xh)[(size_t)dst * 8 + q] = o;
        } else {
            float4* orow = (float4*)out_ext + (size_t)dst * 16;
            orow[q * 2]     = t0;
            orow[q * 2 + 1] = t1;
        }
    }
}

extern "C" void kernel_launch(void* const* d_in, const int* in_sizes, int n_in,
                              void* d_out, int out_size)
{
    const float* emb = (const float*)d_in[0];
    const int*   ei  = (const int*)d_in[1];
    const float* W1  = (const float*)d_in[2];
    const float* b1  = (const float*)d_in[3];
    const float* W2  = (const float*)d_in[4];
    const float* b2  = (const float*)d_in[5];
    const float* W3  = (const float*)d_in[6];
    const float* b3  = (const float*)d_in[7];
    float* out = (float*)d_out;

    const int gemm_blocks = (N_NODES + 127) / 128;
    const int pull_blocks = N_NODES / 8;   // 12500, exact

    // ---- CSR build: one fused kernel ----
    csr_kernel<<<MB, MT>>>(ei);

    // ---- Layer 1: emb -> g_xh ----
    gemm_kernel<<<gemm_blocks, 128>>>(emb, W1, /*xsel=*/0);
    pull_kernel<<<pull_blocks, 256>>>(b1, out, /*mode=*/1);

    // ---- Layer 2: g_xh -> g_xh ----
    gemm_kernel<<<gemm_blocks, 128>>>(emb, W2, /*xsel=*/1);
    pull_kernel<<<pull_blocks, 256>>>(b2, out, /*mode=*/1);

    // ---- Layer 3: g_xh -> d_out (fp32) ----
    gemm_kernel<<<gemm_blocks, 128>>>(emb, W3, /*xsel=*/1);
    pull_kernel<<<pull_blocks, 256>>>(b3, out, /*mode=*/0);
}

// round 10
// speedup vs baseline: 1.3288x; 1.3288x over previous
#include <cuda_runtime.h>
#include <cuda_fp16.h>
#include <math.h>

#define N_NODES 100000
#define N_EDGES 1600000
#define H 64
#define SCAN_T 1024
#define SCAN_B ((N_NODES + SCAN_T - 1) / SCAN_T)   // 98

// Scratch (device globals — no allocation allowed)
__device__ int    g_degi[N_NODES];
__device__ float  g_dinv[N_NODES];
__device__ int    g_rowptr[N_NODES];       // exclusive-within-block partials
__device__ int    g_bsum[SCAN_B];
__device__ int    g_boff[SCAN_B];          // exclusive block offsets
__device__ int    g_rank[N_EDGES];         // edge rank within its dst row
__device__ int    g_ticket;
__device__ int2   g_edge[N_EDGES];         // {src, norm-as-bits}
__device__ __half g_yh[(size_t)N_NODES * H];   // y = xW (fp16, gather target)
__device__ __half g_xh[(size_t)N_NODES * H];   // intermediate layer output (fp16)

__global__ void zero_kernel() {
    int i = blockIdx.x * blockDim.x + threadIdx.x;
    if (i < N_NODES) g_degi[i] = 0;
    if (i == 0) g_ticket = 0;
}

// Histogram over dst; the returned old count is this edge's rank in its row.
__global__ void hist_kernel(const int* __restrict__ ei) {
    int e = blockIdx.x * blockDim.x + threadIdx.x;
    if (e < N_EDGES) g_rank[e] = atomicAdd(&g_degi[ei[N_EDGES + e]], 1);
}

// Per-block scan of degrees (+ fused dinv). Last block to finish also scans
// the 98 block sums into g_boff (decoupled via ticket + threadfence).
__global__ void __launch_bounds__(SCAN_T) scanA_kernel() {
    __shared__ int s[SCAN_T];
    __shared__ int s2[128];
    __shared__ int isLast;
    int t = threadIdx.x;
    int i = blockIdx.x * SCAN_T + t;
    int v = (i < N_NODES) ? g_degi[i] : 0;
    if (i < N_NODES) g_dinv[i] = rsqrtf((float)(v + 1));
    s[t] = v;
    __syncthreads();
    for (int off = 1; off < SCAN_T; off <<= 1) {
        int tmp = 0;
        if (t >= off) tmp = s[t - off];
        __syncthreads();
        if (t >= off) s[t] += tmp;
        __syncthreads();
    }
    if (i < N_NODES) g_rowptr[i] = s[t] - v;  // exclusive within block
    if (t == SCAN_T - 1) g_bsum[blockIdx.x] = s[t];

    if (t == 0) {
        __threadfence();
        int prev = atomicAdd(&g_ticket, 1);
        isLast = (prev == gridDim.x - 1) ? 1 : 0;
    }
    __syncthreads();
    if (!isLast) return;
    __threadfence();  // acquire bsum writes

    int v2 = (t < SCAN_B) ? g_bsum[t] : 0;
    if (t < 128) s2[t] = v2;
    __syncthreads();
    for (int off = 1; off < 128; off <<= 1) {
        int tmp = 0;
        if (t >= off && t < 128) tmp = s2[t - off];
        __syncthreads();
        if (t >= off && t < 128) s2[t] += tmp;
        __syncthreads();
    }
    if (t < SCAN_B) g_boff[t] = s2[t] - v2;  // exclusive
}

// CSR fill; no atomics (rank precomputed by hist), boff applied on the fly.
__global__ void fill_kernel(const int* __restrict__ ei) {
    int e = blockIdx.x * blockDim.x + threadIdx.x;
    if (e >= N_EDGES) return;
    int s = ei[e];
    int d = ei[N_EDGES + e];
    int p = g_rowptr[d] + g_boff[d >> 10] + g_rank[e];
    int2 m;
    m.x = s;
    m.y = __float_as_int(g_dinv[s] * g_dinv[d]);
    g_edge[p] = m;
}

// Tensor-core GEMM: y = x @ W (fp16 in/out, fp32 accumulate).
// Block: 256 threads = 8 warps; 256 rows/block. Each warp: two m16 tiles x 8 n8 tiles.
// Smem rows padded to 72 halves (144B): LDS bank = (4*(lane>>2)+(lane&3)) mod 32,
// all distinct -> conflict-free fragment loads without ldmatrix.
// xsel: 0 = fp32 embeddings (convert), 1 = fp16 g_xh.
__global__ void __launch_bounds__(256, 2) gemm_kernel(
    const float* __restrict__ x_ext, const float* __restrict__ W, int xsel)
{
    __shared__ __half xs[256][72];   // 36864 B
    __shared__ __half Wt[64][72];    // 9216 B : Wt[c][k] = W[k][c]

    const int tid = threadIdx.x;
    const int base = blockIdx.x * 256;

    // Stage W transposed as fp16
    for (int i = tid; i < 64 * 64; i += 256) {
        int k = i >> 6, c = i & 63;
        Wt[c][k] = __float2half(W[i]);
    }

    // Stage one x row per thread (clamp tail reads; outputs are guarded)
    {
        int row = base + tid;
        if (row >= N_NODES) row = N_NODES - 1;
        if (xsel == 0) {
            const float4* xr = (const float4*)x_ext + (size_t)row * 16;
#pragma unroll
            for (int j = 0; j < 16; j++) {
                float4 v = xr[j];
                *(__half2*)&xs[tid][j * 4]     = __floats2half2_rn(v.x, v.y);
                *(__half2*)&xs[tid][j * 4 + 2] = __floats2half2_rn(v.z, v.w);
            }
        } else {
            const uint4* xr = (const uint4*)(g_xh + (size_t)row * H);
#pragma unroll
            for (int j = 0; j < 8; j++)
                *(uint4*)&xs[tid][j * 8] = xr[j];
        }
    }
    __syncthreads();

    const int w = tid >> 5;
    const int lane = tid & 31;
    const int qr = lane >> 2;        // group row 0..7
    const int qc = (lane & 3) * 2;   // k-pair col 0,2,4,6
    const int r0 = w * 32;

    float acc[2][8][4];
#pragma unroll
    for (int t = 0; t < 2; t++)
#pragma unroll
        for (int n = 0; n < 8; n++)
#pragma unroll
            for (int i = 0; i < 4; i++) acc[t][n][i] = 0.f;

#pragma unroll
    for (int ks = 0; ks < 4; ks++) {
        int k0 = ks * 16;
        unsigned a[2][4];
#pragma unroll
        for (int t = 0; t < 2; t++) {
            int rr = r0 + t * 16 + qr;
            a[t][0] = *(const unsigned*)&xs[rr][k0 + qc];
            a[t][1] = *(const unsigned*)&xs[rr + 8][k0 + qc];
            a[t][2] = *(const unsigned*)&xs[rr][k0 + qc + 8];
            a[t][3] = *(const unsigned*)&xs[rr + 8][k0 + qc + 8];
        }
#pragma unroll
        for (int n = 0; n < 8; n++) {
            unsigned b0 = *(const unsigned*)&Wt[n * 8 + qr][k0 + qc];
            unsigned b1 = *(const unsigned*)&Wt[n * 8 + qr][k0 + qc + 8];
#pragma unroll
            for (int t = 0; t < 2; t++) {
                asm("mma.sync.aligned.m16n8k16.row.col.f32.f16.f16.f32 "
                    "{%0,%1,%2,%3}, {%4,%5,%6,%7}, {%8,%9}, {%0,%1,%2,%3};"
                    : "+f"(acc[t][n][0]), "+f"(acc[t][n][1]),
                      "+f"(acc[t][n][2]), "+f"(acc[t][n][3])
                    : "r"(a[t][0]), "r"(a[t][1]), "r"(a[t][2]), "r"(a[t][3]),
                      "r"(b0), "r"(b1));
            }
        }
    }

    // Write y (fp16). D frag: c0,c1 -> row qr, cols qc,qc+1; c2,c3 -> row qr+8.
#pragma unroll
    for (int t = 0; t < 2; t++) {
        int row0 = base + r0 + t * 16 + qr;
        int row1 = row0 + 8;
#pragma unroll
        for (int n = 0; n < 8; n++) {
            int col = n * 8 + qc;
            if (row0 < N_NODES)
                *(__half2*)&g_yh[(size_t)row0 * H + col] =
                    __floats2half2_rn(acc[t][n][0], acc[t][n][1]);
            if (row1 < N_NODES)
                *(__half2*)&g_yh[(size_t)row1 * H + col] =
                    __floats2half2_rn(acc[t][n][2], acc[t][n][3]);
        }
    }
}

// Pull: one warp per dst. q = lane&7 (16B = 8 fp16 cols), h = lane>>3 (4 edge slots).
// t = sum_e y[src_e]*norm_e + y[dst]*dinv^2 + b   (fp32 accumulate)
// mode==1: g_xh[dst] = t (fp16) ; mode==0: out[dst] = t (fp32, final)
__global__ void __launch_bounds__(256) pull_kernel(
    const float* __restrict__ bias, float* __restrict__ out_ext, int mode)
{
    int warp = (blockIdx.x * 256 + threadIdx.x) >> 5;   // grid exact: N_NODES warps
    int dst = warp;
    int lane = threadIdx.x & 31;
    int q = lane & 7;
    int h = lane >> 3;

    int beg = g_rowptr[dst] + g_boff[dst >> 10];
    int end = (dst + 1 < N_NODES) ? (g_rowptr[dst + 1] + g_boff[(dst + 1) >> 10])
                                  : N_EDGES;

    const uint4* y16 = (const uint4*)g_yh;  // 8 uint4 per row

    float4 a0 = make_float4(0.f, 0.f, 0.f, 0.f);
    float4 a1 = make_float4(0.f, 0.f, 0.f, 0.f);

    for (int j = beg + h; j < end; j += 4) {
        int2 m = g_edge[j];
        float nm = __int_as_float(m.y);
        uint4 v = y16[(size_t)m.x * 8 + q];
        const __half2* hp = (const __half2*)&v;
        float2 f0 = __half22float2(hp[0]);
        float2 f1 = __half22float2(hp[1]);
        float2 f2 = __half22float2(hp[2]);
        float2 f3 = __half22float2(hp[3]);
        a0.x = fmaf(f0.x, nm, a0.x); a0.y = fmaf(f0.y, nm, a0.y);
        a0.z = fmaf(f1.x, nm, a0.z); a0.w = fmaf(f1.y, nm, a0.w);
        a1.x = fmaf(f2.x, nm, a1.x); a1.y = fmaf(f2.y, nm, a1.y);
        a1.z = fmaf(f3.x, nm, a1.z); a1.w = fmaf(f3.y, nm, a1.w);
    }

#pragma unroll
    for (int off = 8; off < 32; off <<= 1) {
        a0.x += __shfl_xor_sync(0xFFFFFFFFu, a0.x, off);
        a0.y += __shfl_xor_sync(0xFFFFFFFFu, a0.y, off);
        a0.z += __shfl_xor_sync(0xFFFFFFFFu, a0.z, off);
        a0.w += __shfl_xor_sync(0xFFFFFFFFu, a0.w, off);
        a1.x += __shfl_xor_sync(0xFFFFFFFFu, a1.x, off);
        a1.y += __shfl_xor_sync(0xFFFFFFFFu, a1.y, off);
        a1.z += __shfl_xor_sync(0xFFFFFFFFu, a1.z, off);
        a1.w += __shfl_xor_sync(0xFFFFFFFFu, a1.w, off);
    }

    if (h == 0) {
        float di = g_dinv[dst];
        float s2 = di * di;
        uint4 v = y16[(size_t)dst * 8 + q];
        const __half2* hp = (const __half2*)&v;
        float2 f0 = __half22float2(hp[0]);
        float2 f1 = __half22float2(hp[1]);
        float2 f2 = __half22float2(hp[2]);
        float2 f3 = __half22float2(hp[3]);
        float4 bv0 = ((const float4*)bias)[q * 2];
        float4 bv1 = ((const float4*)bias)[q * 2 + 1];
        float4 t0, t1;
        t0.x = fmaf(f0.x, s2, a0.x) + bv0.x;
        t0.y = fmaf(f0.y, s2, a0.y) + bv0.y;
        t0.z = fmaf(f1.x, s2, a0.z) + bv0.z;
        t0.w = fmaf(f1.y, s2, a0.w) + bv0.w;
        t1.x = fmaf(f2.x, s2, a1.x) + bv1.x;
        t1.y = fmaf(f2.y, s2, a1.y) + bv1.y;
        t1.z = fmaf(f3.x, s2, a1.z) + bv1.z;
        t1.w = fmaf(f3.y, s2, a1.w) + bv1.w;
        if (mode) {
            uint4 o;
            __half2 h0 = __floats2half2_rn(t0.x, t0.y);
            __half2 h1 = __floats2half2_rn(t0.z, t0.w);
            __half2 h2 = __floats2half2_rn(t1.x, t1.y);
            __half2 h3 = __floats2half2_rn(t1.z, t1.w);
            o.x = *(unsigned*)&h0; o.y = *(unsigned*)&h1;
            o.z = *(unsigned*)&h2; o.w = *(unsigned*)&h3;
            ((uint4*)g_xh)[(size_t)dst * 8 + q] = o;
        } else {
            float4* orow = (float4*)out_ext + (size_t)dst * 16;
            orow[q * 2]     = t0;
            orow[q * 2 + 1] = t1;
        }
    }
}

extern "C" void kernel_launch(void* const* d_in, const int* in_sizes, int n_in,
                              void* d_out, int out_size)
{
    const float* emb = (const float*)d_in[0];
    const int*   ei  = (const int*)d_in[1];
    const float* W1  = (const float*)d_in[2];
    const float* b1  = (const float*)d_in[3];
    const float* W2  = (const float*)d_in[4];
    const float* b2  = (const float*)d_in[5];
    const float* W3  = (const float*)d_in[6];
    const float* b3  = (const float*)d_in[7];
    float* out = (float*)d_out;

    const int node_blocks = (N_NODES + 255) / 256;
    const int edge_blocks = (N_EDGES + 255) / 256;
    const int gemm_blocks = (N_NODES + 255) / 256;   // 391
    const int pull_blocks = N_NODES / 8;             // 12500, exact

    // ---- CSR build (round-7 proven path) ----
    zero_kernel<<<node_blocks, 256>>>();
    hist_kernel<<<edge_blocks, 256>>>(ei);
    scanA_kernel<<<SCAN_B, SCAN_T>>>();
    fill_kernel<<<edge_blocks, 256>>>(ei);

    // ---- Layer 1: emb -> g_xh ----
    gemm_kernel<<<gemm_blocks, 256>>>(emb, W1, /*xsel=*/0);
    pull_kernel<<<pull_blocks, 256>>>(b1, out, /*mode=*/1);

    // ---- Layer 2: g_xh -> g_xh ----
    gemm_kernel<<<gemm_blocks, 256>>>(emb, W2, /*xsel=*/1);
    pull_kernel<<<pull_blocks, 256>>>(b2, out, /*mode=*/1);

    // ---- Layer 3: g_xh -> d_out (fp32) ----
    gemm_kernel<<<gemm_blocks, 256>>>(emb, W3, /*xsel=*/1);
    pull_kernel<<<pull_blocks, 256>>>(b3, out, /*mode=*/0);
}

// round 11
// speedup vs baseline: 1.4305x; 1.0766x over previous
#include <cuda_runtime.h>
#include <cuda_fp16.h>
#include <math.h>

#define N_NODES 100000
#define N_EDGES 1600000
#define H 64
#define SCAN_T 1024
#define SCAN_B ((N_NODES + SCAN_T - 1) / SCAN_T)   // 98

// Scratch (device globals — no allocation allowed)
__device__ int    g_degi[N_NODES];
__device__ float  g_dinv[N_NODES];
__device__ int    g_rowptr[N_NODES];       // exclusive-within-block partials
__device__ int    g_bsum[SCAN_B];
__device__ int    g_boff[SCAN_B];          // exclusive block offsets
__device__ int    g_rank[N_EDGES];         // edge rank within its dst row
__device__ int    g_ticket;
__device__ int    g_esrc[N_EDGES];         // CSR: src index only (norm factored out)
__device__ __half g_yh[(size_t)N_NODES * H];   // y' = (xW)*dinv (fp16, gather target)
__device__ __half g_xh[(size_t)N_NODES * H];   // intermediate layer output (fp16)

__global__ void zero_kernel() {
    int i = blockIdx.x * blockDim.x + threadIdx.x;
    if (i < N_NODES) g_degi[i] = 0;
    if (i == 0) g_ticket = 0;
}

// Histogram over dst; the returned old count is this edge's rank in its row.
__global__ void hist_kernel(const int* __restrict__ ei) {
    int e = blockIdx.x * blockDim.x + threadIdx.x;
    if (e < N_EDGES) g_rank[e] = atomicAdd(&g_degi[ei[N_EDGES + e]], 1);
}

// Per-block scan of degrees (+ fused dinv). Last block to finish also scans
// the 98 block sums into g_boff (decoupled via ticket + threadfence).
__global__ void __launch_bounds__(SCAN_T) scanA_kernel() {
    __shared__ int s[SCAN_T];
    __shared__ int s2[128];
    __shared__ int isLast;
    int t = threadIdx.x;
    int i = blockIdx.x * SCAN_T + t;
    int v = (i < N_NODES) ? g_degi[i] : 0;
    if (i < N_NODES) g_dinv[i] = rsqrtf((float)(v + 1));
    s[t] = v;
    __syncthreads();
    for (int off = 1; off < SCAN_T; off <<= 1) {
        int tmp = 0;
        if (t >= off) tmp = s[t - off];
        __syncthreads();
        if (t >= off) s[t] += tmp;
        __syncthreads();
    }
    if (i < N_NODES) g_rowptr[i] = s[t] - v;  // exclusive within block
    if (t == SCAN_T - 1) g_bsum[blockIdx.x] = s[t];

    if (t == 0) {
        __threadfence();
        int prev = atomicAdd(&g_ticket, 1);
        isLast = (prev == gridDim.x - 1) ? 1 : 0;
    }
    __syncthreads();
    if (!isLast) return;
    __threadfence();  // acquire bsum writes

    int v2 = (t < SCAN_B) ? g_bsum[t] : 0;
    if (t < 128) s2[t] = v2;
    __syncthreads();
    for (int off = 1; off < 128; off <<= 1) {
        int tmp = 0;
        if (t >= off && t < 128) tmp = s2[t - off];
        __syncthreads();
        if (t >= off && t < 128) s2[t] += tmp;
        __syncthreads();
    }
    if (t < SCAN_B) g_boff[t] = s2[t] - v2;  // exclusive
}

// CSR fill: pure permutation of src indices (no atomics, no norm math).
__global__ void fill_kernel(const int* __restrict__ ei) {
    int e = blockIdx.x * blockDim.x + threadIdx.x;
    if (e >= N_EDGES) return;
    int s = ei[e];
    int d = ei[N_EDGES + e];
    int p = g_rowptr[d] + g_boff[d >> 10] + g_rank[e];
    g_esrc[p] = s;
}

// Tensor-core GEMM: y' = (x @ W) * dinv[row]  (fp16 out, fp32 accumulate).
// Block: 256 threads = 8 warps; 256 rows/block. Each warp: two m16 tiles x 8 n8 tiles.
// Smem rows padded to 72 halves: conflict-free fragment loads without ldmatrix.
// xsel: 0 = fp32 embeddings (convert), 1 = fp16 g_xh.
__global__ void __launch_bounds__(256, 2) gemm_kernel(
    const float* __restrict__ x_ext, const float* __restrict__ W, int xsel)
{
    __shared__ __half xs[256][72];   // 36864 B
    __shared__ __half Wt[64][72];    // 9216 B : Wt[c][k] = W[k][c]

    const int tid = threadIdx.x;
    const int base = blockIdx.x * 256;

    // Stage W transposed as fp16
    for (int i = tid; i < 64 * 64; i += 256) {
        int k = i >> 6, c = i & 63;
        Wt[c][k] = __float2half(W[i]);
    }

    // Stage one x row per thread (clamp tail reads; outputs are guarded)
    {
        int row = base + tid;
        if (row >= N_NODES) row = N_NODES - 1;
        if (xsel == 0) {
            const float4* xr = (const float4*)x_ext + (size_t)row * 16;
#pragma unroll
            for (int j = 0; j < 16; j++) {
                float4 v = xr[j];
                *(__half2*)&xs[tid][j * 4]     = __floats2half2_rn(v.x, v.y);
                *(__half2*)&xs[tid][j * 4 + 2] = __floats2half2_rn(v.z, v.w);
            }
        } else {
            const uint4* xr = (const uint4*)(g_xh + (size_t)row * H);
#pragma unroll
            for (int j = 0; j < 8; j++)
                *(uint4*)&xs[tid][j * 8] = xr[j];
        }
    }
    __syncthreads();

    const int w = tid >> 5;
    const int lane = tid & 31;
    const int qr = lane >> 2;        // group row 0..7
    const int qc = (lane & 3) * 2;   // k-pair col 0,2,4,6
    const int r0 = w * 32;

    float acc[2][8][4];
#pragma unroll
    for (int t = 0; t < 2; t++)
#pragma unroll
        for (int n = 0; n < 8; n++)
#pragma unroll
            for (int i = 0; i < 4; i++) acc[t][n][i] = 0.f;

#pragma unroll
    for (int ks = 0; ks < 4; ks++) {
        int k0 = ks * 16;
        unsigned a[2][4];
#pragma unroll
        for (int t = 0; t < 2; t++) {
            int rr = r0 + t * 16 + qr;
            a[t][0] = *(const unsigned*)&xs[rr][k0 + qc];
            a[t][1] = *(const unsigned*)&xs[rr + 8][k0 + qc];
            a[t][2] = *(const unsigned*)&xs[rr][k0 + qc + 8];
            a[t][3] = *(const unsigned*)&xs[rr + 8][k0 + qc + 8];
        }
#pragma unroll
        for (int n = 0; n < 8; n++) {
            unsigned b0 = *(const unsigned*)&Wt[n * 8 + qr][k0 + qc];
            unsigned b1 = *(const unsigned*)&Wt[n * 8 + qr][k0 + qc + 8];
#pragma unroll
            for (int t = 0; t < 2; t++) {
                asm("mma.sync.aligned.m16n8k16.row.col.f32.f16.f16.f32 "
                    "{%0,%1,%2,%3}, {%4,%5,%6,%7}, {%8,%9}, {%0,%1,%2,%3};"
                    : "+f"(acc[t][n][0]), "+f"(acc[t][n][1]),
                      "+f"(acc[t][n][2]), "+f"(acc[t][n][3])
                    : "r"(a[t][0]), "r"(a[t][1]), "r"(a[t][2]), "r"(a[t][3]),
                      "r"(b0), "r"(b1));
            }
        }
    }

    // Write y' = y * dinv (fp16). c0,c1 -> row qr; c2,c3 -> row qr+8.
#pragma unroll
    for (int t = 0; t < 2; t++) {
        int row0 = base + r0 + t * 16 + qr;
        int row1 = row0 + 8;
        float d0 = (row0 < N_NODES) ? g_dinv[row0] : 0.f;
        float d1 = (row1 < N_NODES) ? g_dinv[row1] : 0.f;
#pragma unroll
        for (int n = 0; n < 8; n++) {
            int col = n * 8 + qc;
            if (row0 < N_NODES)
                *(__half2*)&g_yh[(size_t)row0 * H + col] =
                    __floats2half2_rn(acc[t][n][0] * d0, acc[t][n][1] * d0);
            if (row1 < N_NODES)
                *(__half2*)&g_yh[(size_t)row1 * H + col] =
                    __floats2half2_rn(acc[t][n][2] * d1, acc[t][n][3] * d1);
        }
    }
}

// Pull: one warp per dst. q = lane&7 (16B = 8 fp16 cols), h = lane>>3 (4 edge slots).
// t = dinv[dst] * ( sum_e y'[src_e] + y'[dst] ) + b   (fp32 accumulate)
// mode==1: g_xh[dst] = t (fp16) ; mode==0: out[dst] = t (fp32, final)
__global__ void __launch_bounds__(256) pull_kernel(
    const float* __restrict__ bias, float* __restrict__ out_ext, int mode)
{
    int warp = (blockIdx.x * 256 + threadIdx.x) >> 5;   // grid exact: N_NODES warps
    int dst = warp;
    int lane = threadIdx.x & 31;
    int q = lane & 7;
    int h = lane >> 3;

    int beg = g_rowptr[dst] + g_boff[dst >> 10];
    int end = (dst + 1 < N_NODES) ? (g_rowptr[dst + 1] + g_boff[(dst + 1) >> 10])
                                  : N_EDGES;

    const uint4* y16 = (const uint4*)g_yh;  // 8 uint4 per row

    float4 a0 = make_float4(0.f, 0.f, 0.f, 0.f);
    float4 a1 = make_float4(0.f, 0.f, 0.f, 0.f);

    for (int j = beg + h; j < end; j += 4) {
        int src = g_esrc[j];
        uint4 v = y16[(size_t)src * 8 + q];
        const __half2* hp = (const __half2*)&v;
        float2 f0 = __half22float2(hp[0]);
        float2 f1 = __half22float2(hp[1]);
        float2 f2 = __half22float2(hp[2]);
        float2 f3 = __half22float2(hp[3]);
        a0.x += f0.x; a0.y += f0.y;
        a0.z += f1.x; a0.w += f1.y;
        a1.x += f2.x; a1.y += f2.y;
        a1.z += f3.x; a1.w += f3.y;
    }

#pragma unroll
    for (int off = 8; off < 32; off <<= 1) {
        a0.x += __shfl_xor_sync(0xFFFFFFFFu, a0.x, off);
        a0.y += __shfl_xor_sync(0xFFFFFFFFu, a0.y, off);
        a0.z += __shfl_xor_sync(0xFFFFFFFFu, a0.z, off);
        a0.w += __shfl_xor_sync(0xFFFFFFFFu, a0.w, off);
        a1.x += __shfl_xor_sync(0xFFFFFFFFu, a1.x, off);
        a1.y += __shfl_xor_sync(0xFFFFFFFFu, a1.y, off);
        a1.z += __shfl_xor_sync(0xFFFFFFFFu, a1.z, off);
        a1.w += __shfl_xor_sync(0xFFFFFFFFu, a1.w, off);
    }

    if (h == 0) {
        float di = g_dinv[dst];
        uint4 v = y16[(size_t)dst * 8 + q];
        const __half2* hp = (const __half2*)&v;
        float2 f0 = __half22float2(hp[0]);
        float2 f1 = __half22float2(hp[1]);
        float2 f2 = __half22float2(hp[2]);
        float2 f3 = __half22float2(hp[3]);
        float4 bv0 = ((const float4*)bias)[q * 2];
        float4 bv1 = ((const float4*)bias)[q * 2 + 1];
        float4 t0, t1;
        t0.x = fmaf(a0.x + f0.x, di, bv0.x);
        t0.y = fmaf(a0.y + f0.y, di, bv0.y);
        t0.z = fmaf(a0.z + f1.x, di, bv0.z);
        t0.w = fmaf(a0.w + f1.y, di, bv0.w);
        t1.x = fmaf(a1.x + f2.x, di, bv1.x);
        t1.y = fmaf(a1.y + f2.y, di, bv1.y);
        t1.z = fmaf(a1.z + f3.x, di, bv1.z);
        t1.w = fmaf(a1.w + f3.y, di, bv1.w);
        if (mode) {
            uint4 o;
            __half2 h0 = __floats2half2_rn(t0.x, t0.y);
            __half2 h1 = __floats2half2_rn(t0.z, t0.w);
            __half2 h2 = __floats2half2_rn(t1.x, t1.y);
            __half2 h3 = __floats2half2_rn(t1.z, t1.w);
            o.x = *(unsigned*)&h0; o.y = *(unsigned*)&h1;
            o.z = *(unsigned*)&h2; o.w = *(unsigned*)&h3;
            ((uint4*)g_xh)[(size_t)dst * 8 + q] = o;
        } else {
            float4* orow = (float4*)out_ext + (size_t)dst * 16;
            orow[q * 2]     = t0;
            orow[q * 2 + 1] = t1;
        }
    }
}

extern "C" void kernel_launch(void* const* d_in, const int* in_sizes, int n_in,
                              void* d_out, int out_size)
{
    const float* emb = (const float*)d_in[0];
    const int*   ei  = (const int*)d_in[1];
    const float* W1  = (const float*)d_in[2];
    const float* b1  = (const float*)d_in[3];
    const float* W2  = (const float*)d_in[4];
    const float* b2  = (const float*)d_in[5];
    const float* W3  = (const float*)d_in[6];
    const float* b3  = (const float*)d_in[7];
    float* out = (float*)d_out;

    const int node_blocks = (N_NODES + 255) / 256;
    const int edge_blocks = (N_EDGES + 255) / 256;
    const int gemm_blocks = (N_NODES + 255) / 256;   // 391
    const int pull_blocks = N_NODES / 8;             // 12500, exact

    // ---- CSR build ----
    zero_kernel<<<node_blocks, 256>>>();
    hist_kernel<<<edge_blocks, 256>>>(ei);
    scanA_kernel<<<SCAN_B, SCAN_T>>>();
    fill_kernel<<<edge_blocks, 256>>>(ei);

    // ---- Layer 1: emb -> g_xh ----
    gemm_kernel<<<gemm_blocks, 256>>>(emb, W1, /*xsel=*/0);
    pull_kernel<<<pull_blocks, 256>>>(b1, out, /*mode=*/1);

    // ---- Layer 2: g_xh -> g_xh ----
    gemm_kernel<<<gemm_blocks, 256>>>(emb, W2, /*xsel=*/1);
    pull_kernel<<<pull_blocks, 256>>>(b2, out, /*mode=*/1);

    // ---- Layer 3: g_xh -> d_out (fp32) ----
    gemm_kernel<<<gemm_blocks, 256>>>(emb, W3, /*xsel=*/1);
    pull_kernel<<<pull_blocks, 256>>>(b3, out, /*mode=*/0);
}

// round 12
// speedup vs baseline: 1.5810x; 1.1052x over previous
#include <cuda_runtime.h>
#include <cuda_fp16.h>
#include <math.h>

#define N_NODES 100000
#define N_EDGES 1600000
#define H 64
#define SCAN_T 1024
#define SCAN_B ((N_NODES + SCAN_T - 1) / SCAN_T)   // 98

// Scratch (device globals — no allocation allowed)
__device__ int    g_degi[N_NODES];
__device__ float  g_dinv[N_NODES];
__device__ int    g_rowptr[N_NODES];       // exclusive-within-block partials
__device__ int    g_bsum[SCAN_B];
__device__ int    g_boff[SCAN_B];          // exclusive block offsets
__device__ int    g_rank[N_EDGES];         // edge rank within its dst row
__device__ int    g_ticket;
__device__ int    g_esrc[N_EDGES];         // CSR: src index only (norm factored out)
__device__ __half g_yh[(size_t)N_NODES * H];   // y' = (xW)*dinv (fp16, gather target)
__device__ __half g_xh[(size_t)N_NODES * H];   // intermediate layer output (fp16)

__global__ void zero_kernel() {
    int i = blockIdx.x * blockDim.x + threadIdx.x;
    if (i < N_NODES) g_degi[i] = 0;
    if (i == 0) g_ticket = 0;
}

// Histogram over dst (2 edges/thread, int2); old count = edge's rank in its row.
__global__ void hist_kernel(const int* __restrict__ ei) {
    int i = blockIdx.x * blockDim.x + threadIdx.x;
    int e = 2 * i;
    if (e + 1 < N_EDGES) {
        int2 d = *(const int2*)&ei[N_EDGES + e];
        int r0 = atomicAdd(&g_degi[d.x], 1);
        int r1 = atomicAdd(&g_degi[d.y], 1);
        *(int2*)&g_rank[e] = make_int2(r0, r1);
    }
}

// Per-block scan of degrees (+ fused dinv). Last block to finish also scans
// the 98 block sums into g_boff (decoupled via ticket + threadfence).
__global__ void __launch_bounds__(SCAN_T) scanA_kernel() {
    __shared__ int s[SCAN_T];
    __shared__ int s2[128];
    __shared__ int isLast;
    int t = threadIdx.x;
    int i = blockIdx.x * SCAN_T + t;
    int v = (i < N_NODES) ? g_degi[i] : 0;
    if (i < N_NODES) g_dinv[i] = rsqrtf((float)(v + 1));
    s[t] = v;
    __syncthreads();
    for (int off = 1; off < SCAN_T; off <<= 1) {
        int tmp = 0;
        if (t >= off) tmp = s[t - off];
        __syncthreads();
        if (t >= off) s[t] += tmp;
        __syncthreads();
    }
    if (i < N_NODES) g_rowptr[i] = s[t] - v;  // exclusive within block
    if (t == SCAN_T - 1) g_bsum[blockIdx.x] = s[t];

    if (t == 0) {
        __threadfence();
        int prev = atomicAdd(&g_ticket, 1);
        isLast = (prev == gridDim.x - 1) ? 1 : 0;
    }
    __syncthreads();
    if (!isLast) return;
    __threadfence();  // acquire bsum writes

    int v2 = (t < SCAN_B) ? g_bsum[t] : 0;
    if (t < 128) s2[t] = v2;
    __syncthreads();
    for (int off = 1; off < 128; off <<= 1) {
        int tmp = 0;
        if (t >= off && t < 128) tmp = s2[t - off];
        __syncthreads();
        if (t >= off && t < 128) s2[t] += tmp;
        __syncthreads();
    }
    if (t < SCAN_B) g_boff[t] = s2[t] - v2;  // exclusive
}

// CSR fill: pure permutation of src indices, 2 edges/thread.
__global__ void fill_kernel(const int* __restrict__ ei) {
    int i = blockIdx.x * blockDim.x + threadIdx.x;
    int e = 2 * i;
    if (e + 1 < N_EDGES) {
        int2 sv = *(const int2*)&ei[e];
        int2 dv = *(const int2*)&ei[N_EDGES + e];
        int2 rv = *(const int2*)&g_rank[e];
        g_esrc[g_rowptr[dv.x] + g_boff[dv.x >> 10] + rv.x] = sv.x;
        g_esrc[g_rowptr[dv.y] + g_boff[dv.y >> 10] + rv.y] = sv.y;
    }
}

// Tensor-core GEMM: y' = (x @ W) * dinv[row]  (fp16 out, fp32 accumulate).
// 128 threads = 4 warps = 128 rows/block. A fragments loaded DIRECTLY from
// global (4B/lane; the warp's a-words cover each 32B sector exactly once),
// only Wt staged in smem. No x smem, no barrier in the hot path.
// xsel: 0 = fp32 embeddings (convert in flight), 1 = fp16 g_xh.
__global__ void __launch_bounds__(128, 4) gemm_kernel(
    const float* __restrict__ x_ext, const float* __restrict__ W, int xsel)
{
    __shared__ __half Wt[64][72];    // 9216 B : Wt[c][k] = W[k][c]

    const int tid = threadIdx.x;
    for (int i = tid; i < 64 * 64; i += 128) {
        int k = i >> 6, c = i & 63;
        Wt[c][k] = __float2half(W[i]);
    }
    __syncthreads();

    const int w = tid >> 5;
    const int lane = tid & 31;
    const int qr = lane >> 2;        // group row 0..7
    const int qc = (lane & 3) * 2;   // k-pair col 0,2,4,6
    const int r0 = blockIdx.x * 128 + w * 32;

    // Per-tile rows (clamped for loads; stores guarded)
    int rowa[2], rowb[2];
#pragma unroll
    for (int t = 0; t < 2; t++) {
        int ra = r0 + t * 16 + qr;
        int rb = ra + 8;
        rowa[t] = (ra < N_NODES) ? ra : N_NODES - 1;
        rowb[t] = (rb < N_NODES) ? rb : N_NODES - 1;
    }

    float acc[2][8][4];
#pragma unroll
    for (int t = 0; t < 2; t++)
#pragma unroll
        for (int n = 0; n < 8; n++)
#pragma unroll
            for (int i = 0; i < 4; i++) acc[t][n][i] = 0.f;

#pragma unroll
    for (int ks = 0; ks < 4; ks++) {
        int k0 = ks * 16;
        unsigned a[2][4];
        if (xsel == 0) {
#pragma unroll
            for (int t = 0; t < 2; t++) {
                float2 v0 = *(const float2*)&x_ext[(size_t)rowa[t] * H + k0 + qc];
                float2 v1 = *(const float2*)&x_ext[(size_t)rowb[t] * H + k0 + qc];
                float2 v2 = *(const float2*)&x_ext[(size_t)rowa[t] * H + k0 + qc + 8];
                float2 v3 = *(const float2*)&x_ext[(size_t)rowb[t] * H + k0 + qc + 8];
                __half2 h0 = __floats2half2_rn(v0.x, v0.y);
                __half2 h1 = __floats2half2_rn(v1.x, v1.y);
                __half2 h2 = __floats2half2_rn(v2.x, v2.y);
                __half2 h3 = __floats2half2_rn(v3.x, v3.y);
                a[t][0] = *(unsigned*)&h0;
                a[t][1] = *(unsigned*)&h1;
                a[t][2] = *(unsigned*)&h2;
                a[t][3] = *(unsigned*)&h3;
            }
        } else {
#pragma unroll
            for (int t = 0; t < 2; t++) {
                a[t][0] = *(const unsigned*)&g_xh[(size_t)rowa[t] * H + k0 + qc];
                a[t][1] = *(const unsigned*)&g_xh[(size_t)rowb[t] * H + k0 + qc];
                a[t][2] = *(const unsigned*)&g_xh[(size_t)rowa[t] * H + k0 + qc + 8];
                a[t][3] = *(const unsigned*)&g_xh[(size_t)rowb[t] * H + k0 + qc + 8];
            }
        }
#pragma unroll
        for (int n = 0; n < 8; n++) {
            unsigned b0 = *(const unsigned*)&Wt[n * 8 + qr][k0 + qc];
            unsigned b1 = *(const unsigned*)&Wt[n * 8 + qr][k0 + qc + 8];
#pragma unroll
            for (int t = 0; t < 2; t++) {
                asm("mma.sync.aligned.m16n8k16.row.col.f32.f16.f16.f32 "
                    "{%0,%1,%2,%3}, {%4,%5,%6,%7}, {%8,%9}, {%0,%1,%2,%3};"
                    : "+f"(acc[t][n][0]), "+f"(acc[t][n][1]),
                      "+f"(acc[t][n][2]), "+f"(acc[t][n][3])
                    : "r"(a[t][0]), "r"(a[t][1]), "r"(a[t][2]), "r"(a[t][3]),
                      "r"(b0), "r"(b1));
            }
        }
    }

    // Write y' = y * dinv (fp16). c0,c1 -> row qr; c2,c3 -> row qr+8.
#pragma unroll
    for (int t = 0; t < 2; t++) {
        int row0 = r0 + t * 16 + qr;
        int row1 = row0 + 8;
        float d0 = (row0 < N_NODES) ? g_dinv[row0] : 0.f;
        float d1 = (row1 < N_NODES) ? g_dinv[row1] : 0.f;
#pragma unroll
        for (int n = 0; n < 8; n++) {
            int col = n * 8 + qc;
            if (row0 < N_NODES)
                *(__half2*)&g_yh[(size_t)row0 * H + col] =
                    __floats2half2_rn(acc[t][n][0] * d0, acc[t][n][1] * d0);
            if (row1 < N_NODES)
                *(__half2*)&g_yh[(size_t)row1 * H + col] =
                    __floats2half2_rn(acc[t][n][2] * d1, acc[t][n][3] * d1);
        }
    }
}

// Pull: one warp per dst. q = lane&7 (16B = 8 fp16 cols), h = lane>>3 (4 edge slots).
// t = dinv[dst] * ( sum_e y'[src_e] + y'[dst] ) + b   (fp32 accumulate)
// mode==1: g_xh[dst] = t (fp16) ; mode==0: out[dst] = t (fp32, final)
__global__ void __launch_bounds__(256) pull_kernel(
    const float* __restrict__ bias, float* __restrict__ out_ext, int mode)
{
    int warp = (blockIdx.x * 256 + threadIdx.x) >> 5;   // grid exact: N_NODES warps
    int dst = warp;
    int lane = threadIdx.x & 31;
    int q = lane & 7;
    int h = lane >> 3;

    int beg = g_rowptr[dst] + g_boff[dst >> 10];
    int end = (dst + 1 < N_NODES) ? (g_rowptr[dst + 1] + g_boff[(dst + 1) >> 10])
                                  : N_EDGES;

    const uint4* y16 = (const uint4*)g_yh;  // 8 uint4 per row

    float4 a0 = make_float4(0.f, 0.f, 0.f, 0.f);
    float4 a1 = make_float4(0.f, 0.f, 0.f, 0.f);

#pragma unroll 2
    for (int j = beg + h; j < end; j += 4) {
        int src = __ldg(&g_esrc[j]);
        uint4 v = y16[(size_t)src * 8 + q];
        const __half2* hp = (const __half2*)&v;
        float2 f0 = __half22float2(hp[0]);
        float2 f1 = __half22float2(hp[1]);
        float2 f2 = __half22float2(hp[2]);
        float2 f3 = __half22float2(hp[3]);
        a0.x += f0.x; a0.y += f0.y;
        a0.z += f1.x; a0.w += f1.y;
        a1.x += f2.x; a1.y += f2.y;
        a1.z += f3.x; a1.w += f3.y;
    }

#pragma unroll
    for (int off = 8; off < 32; off <<= 1) {
        a0.x += __shfl_xor_sync(0xFFFFFFFFu, a0.x, off);
        a0.y += __shfl_xor_sync(0xFFFFFFFFu, a0.y, off);
        a0.z += __shfl_xor_sync(0xFFFFFFFFu, a0.z, off);
        a0.w += __shfl_xor_sync(0xFFFFFFFFu, a0.w, off);
        a1.x += __shfl_xor_sync(0xFFFFFFFFu, a1.x, off);
        a1.y += __shfl_xor_sync(0xFFFFFFFFu, a1.y, off);
        a1.z += __shfl_xor_sync(0xFFFFFFFFu, a1.z, off);
        a1.w += __shfl_xor_sync(0xFFFFFFFFu, a1.w, off);
    }

    if (h == 0) {
        float di = g_dinv[dst];
        uint4 v = y16[(size_t)dst * 8 + q];
        const __half2* hp = (const __half2*)&v;
        float2 f0 = __half22float2(hp[0]);
        float2 f1 = __half22float2(hp[1]);
        float2 f2 = __half22float2(hp[2]);
        float2 f3 = __half22float2(hp[3]);
        float4 bv0 = ((const float4*)bias)[q * 2];
        float4 bv1 = ((const float4*)bias)[q * 2 + 1];
        float4 t0, t1;
        t0.x = fmaf(a0.x + f0.x, di, bv0.x);
        t0.y = fmaf(a0.y + f0.y, di, bv0.y);
        t0.z = fmaf(a0.z + f1.x, di, bv0.z);
        t0.w = fmaf(a0.w + f1.y, di, bv0.w);
        t1.x = fmaf(a1.x + f2.x, di, bv1.x);
        t1.y = fmaf(a1.y + f2.y, di, bv1.y);
        t1.z = fmaf(a1.z + f3.x, di, bv1.z);
        t1.w = fmaf(a1.w + f3.y, di, bv1.w);
        if (mode) {
            uint4 o;
            __half2 h0 = __floats2half2_rn(t0.x, t0.y);
            __half2 h1 = __floats2half2_rn(t0.z, t0.w);
            __half2 h2 = __floats2half2_rn(t1.x, t1.y);
            __half2 h3 = __floats2half2_rn(t1.z, t1.w);
            o.x = *(unsigned*)&h0; o.y = *(unsigned*)&h1;
            o.z = *(unsigned*)&h2; o.w = *(unsigned*)&h3;
            ((uint4*)g_xh)[(size_t)dst * 8 + q] = o;
        } else {
            float4* orow = (float4*)out_ext + (size_t)dst * 16;
            orow[q * 2]     = t0;
            orow[q * 2 + 1] = t1;
        }
    }
}

extern "C" void kernel_launch(void* const* d_in, const int* in_sizes, int n_in,
                              void* d_out, int out_size)
{
    const float* emb = (const float*)d_in[0];
    const int*   ei  = (const int*)d_in[1];
    const float* W1  = (const float*)d_in[2];
    const float* b1  = (const float*)d_in[3];
    const float* W2  = (const float*)d_in[4];
    const float* b2  = (const float*)d_in[5];
    const float* W3  = (const float*)d_in[6];
    const float* b3  = (const float*)d_in[7];
    float* out = (float*)d_out;

    const int node_blocks = (N_NODES + 255) / 256;
    const int edge2_blocks = (N_EDGES / 2 + 255) / 256;   // 3125
    const int gemm_blocks = (N_NODES + 127) / 128;        // 782
    const int pull_blocks = N_NODES / 8;                  // 12500, exact

    // ---- CSR build ----
    zero_kernel<<<node_blocks, 256>>>();
    hist_kernel<<<edge2_blocks, 256>>>(ei);
    scanA_kernel<<<SCAN_B, SCAN_T>>>();
    fill_kernel<<<edge2_blocks, 256>>>(ei);

    // ---- Layer 1: emb -> g_xh ----
    gemm_kernel<<<gemm_blocks, 128>>>(emb, W1, /*xsel=*/0);
    pull_kernel<<<pull_blocks, 256>>>(b1, out, /*mode=*/1);

    // ---- Layer 2: g_xh -> g_xh ----
    gemm_kernel<<<gemm_blocks, 128>>>(emb, W2, /*xsel=*/1);
    pull_kernel<<<pull_blocks, 256>>>(b2, out, /*mode=*/1);

    // ---- Layer 3: g_xh -> d_out (fp32) ----
    gemm_kernel<<<gemm_blocks, 128>>>(emb, W3, /*xsel=*/1);
    pull_kernel<<<pull_blocks, 256>>>(b3, out, /*mode=*/0);
}